// round 2
// baseline (speedup 1.0000x reference)
#include <cuda_runtime.h>
#include <math.h>

#define T_TOK 8192
#define DIM 1024
#define NEXP 16
#define TOPK 2
#define INTER 2048

#define TM 64
#define TN 128
#define TKC 16

// ---------------- device scratch (static globals; no allocation) ----------------
__device__ int   g_cnt[NEXP];
__device__ int   g_rows[NEXP][T_TOK];   // value = 2*token + slot
__device__ float g_wt[NEXP][T_TOK];
__device__ float g_H[(size_t)T_TOK * TOPK * INTER];   // 134 MB intermediate

// ---------------- kernel 0: reset counters + zero output ----------------
__global__ void zero_kernel(float* __restrict__ y) {
    int i = blockIdx.x * blockDim.x + threadIdx.x;
    if (i < NEXP) g_cnt[i] = 0;
    if (i < T_TOK * DIM / 4) {
        float4 z = make_float4(0.f, 0.f, 0.f, 0.f);
        reinterpret_cast<float4*>(y)[i] = z;
    }
}

// ---------------- kernel 1: gate (logits -> top2 -> pair softmax -> lists) ------
__global__ void gate_kernel(const float* __restrict__ x,
                            const float* __restrict__ Wg,
                            const float* __restrict__ bg) {
    int t = blockIdx.x;
    int tid = threadIdx.x;            // 128 threads
    int e = tid & 15;
    int c = tid >> 4;                 // 8 chunks of 128
    __shared__ float part[8][17];
    __shared__ float sc[16];

    const float* xr = x + (size_t)t * DIM;
    const float* wc = Wg + e;
    float s = 0.f;
    int d0 = c * 128;
#pragma unroll 4
    for (int d = 0; d < 128; d++)
        s = fmaf(xr[d0 + d], wc[(size_t)(d0 + d) * NEXP], s);
    part[c][e] = s;
    __syncthreads();

    if (tid < 16) {
        float v = bg[tid];
#pragma unroll
        for (int cc = 0; cc < 8; cc++) v += part[cc][tid];
        sc[tid] = v;
    }
    __syncthreads();

    if (tid == 0) {
        int i1 = 0; float v1 = sc[0];
#pragma unroll
        for (int j = 1; j < 16; j++) if (sc[j] > v1) { v1 = sc[j]; i1 = j; }
        int i2 = -1; float v2 = -3.0e38f;
#pragma unroll
        for (int j = 0; j < 16; j++) if (j != i1 && sc[j] > v2) { v2 = sc[j]; i2 = j; }
        // softmax -> top2 -> renormalize  ==  2-way softmax over (v1, v2)
        float r  = expf(v2 - v1);     // <= 1, stable
        float w1 = 1.f / (1.f + r);
        float w2 = r   / (1.f + r);
        int p1 = atomicAdd(&g_cnt[i1], 1);
        g_rows[i1][p1] = 2 * t;     g_wt[i1][p1] = w1;
        int p2 = atomicAdd(&g_cnt[i2], 1);
        g_rows[i2][p2] = 2 * t + 1; g_wt[i2][p2] = w2;
    }
}

// ---------------- kernel 2: up projection, fused W1/W3 + SiLU*mul ---------------
// grid: (INTER/TN, T_TOK/TM, NEXP), 256 threads
__global__ __launch_bounds__(256)
void up_kernel(const float* __restrict__ x,
               const float* __restrict__ W1, const float* __restrict__ b1,
               const float* __restrict__ W3, const float* __restrict__ b3) {
    int e = blockIdx.z;
    int cnt = g_cnt[e];
    int m0 = blockIdx.y * TM;
    if (m0 >= cnt) return;
    int n0 = blockIdx.x * TN;

    __shared__ float sA[TKC][TM + 4];
    __shared__ float sB1[TKC][TN];
    __shared__ float sB3[TKC][TN];
    __shared__ int   sTokRow[TM];   // token index (x row), -1 if invalid
    __shared__ int   sOutRow[TM];   // H row (2t+slot), -1 if invalid

    int tid = threadIdx.x;
    if (tid < TM) {
        int m = m0 + tid;
        if (m < cnt) { int r = g_rows[e][m]; sTokRow[tid] = r >> 1; sOutRow[tid] = r; }
        else         { sTokRow[tid] = -1;    sOutRow[tid] = -1; }
    }
    __syncthreads();

    const float* W1e = W1 + (size_t)e * DIM * INTER + n0;
    const float* W3e = W3 + (size_t)e * DIM * INTER + n0;

    int mb = (tid >> 5) * 8;       // 8 warps -> 8-row groups
    int nb = (tid & 31) * 4;       // 32 lanes * 4 cols

    // A loader mapping: 256 threads load 64 rows x 16 k as one float4 each
    int lr = tid >> 2;             // row 0..63
    int lq = tid & 3;              // float4 slot in k
    int myTok = sTokRow[lr];
    const float* aptr = (myTok >= 0) ? (x + (size_t)myTok * DIM + lq * 4) : x;

    // B loader mapping: 2 float4 per thread per B matrix
    int kb  = tid >> 5;            // 0..7
    int nbc = (tid & 31) * 4;

    float acc1[8][4]; float acc3[8][4];
#pragma unroll
    for (int i = 0; i < 8; i++)
#pragma unroll
        for (int j = 0; j < 4; j++) { acc1[i][j] = 0.f; acc3[i][j] = 0.f; }

    for (int k0 = 0; k0 < DIM; k0 += TKC) {
        float4 av = make_float4(0.f, 0.f, 0.f, 0.f);
        if (myTok >= 0) av = *reinterpret_cast<const float4*>(aptr + k0);
        sA[lq * 4 + 0][lr] = av.x;
        sA[lq * 4 + 1][lr] = av.y;
        sA[lq * 4 + 2][lr] = av.z;
        sA[lq * 4 + 3][lr] = av.w;

        *reinterpret_cast<float4*>(&sB1[kb][nbc]) =
            *reinterpret_cast<const float4*>(W1e + (size_t)(k0 + kb) * INTER + nbc);
        *reinterpret_cast<float4*>(&sB1[kb + 8][nbc]) =
            *reinterpret_cast<const float4*>(W1e + (size_t)(k0 + kb + 8) * INTER + nbc);
        *reinterpret_cast<float4*>(&sB3[kb][nbc]) =
            *reinterpret_cast<const float4*>(W3e + (size_t)(k0 + kb) * INTER + nbc);
        *reinterpret_cast<float4*>(&sB3[kb + 8][nbc]) =
            *reinterpret_cast<const float4*>(W3e + (size_t)(k0 + kb + 8) * INTER + nbc);
        __syncthreads();

#pragma unroll
        for (int kk = 0; kk < TKC; kk++) {
            float a[8], u1[4], u3[4];
#pragma unroll
            for (int i = 0; i < 8; i++) a[i] = sA[kk][mb + i];
#pragma unroll
            for (int j = 0; j < 4; j++) { u1[j] = sB1[kk][nb + j]; u3[j] = sB3[kk][nb + j]; }
#pragma unroll
            for (int i = 0; i < 8; i++)
#pragma unroll
                for (int j = 0; j < 4; j++) {
                    acc1[i][j] = fmaf(a[i], u1[j], acc1[i][j]);
                    acc3[i][j] = fmaf(a[i], u3[j], acc3[i][j]);
                }
        }
        __syncthreads();
    }

    // epilogue: h = silu(z1 + b1) * (z3 + b3) -> H[2t+slot]
    const float4 bv1 = *reinterpret_cast<const float4*>(b1 + (size_t)e * INTER + n0 + nb);
    const float4 bv3 = *reinterpret_cast<const float4*>(b3 + (size_t)e * INTER + n0 + nb);
    float b1a[4] = {bv1.x, bv1.y, bv1.z, bv1.w};
    float b3a[4] = {bv3.x, bv3.y, bv3.z, bv3.w};
#pragma unroll
    for (int i = 0; i < 8; i++) {
        int r = sOutRow[mb + i];
        if (r < 0) continue;
        float4 hv;
        float* h = &hv.x;
#pragma unroll
        for (int j = 0; j < 4; j++) {
            float z1 = acc1[i][j] + b1a[j];
            float z3 = acc3[i][j] + b3a[j];
            h[j] = (z1 / (1.f + expf(-z1))) * z3;
        }
        *reinterpret_cast<float4*>(&g_H[(size_t)r * INTER + n0 + nb]) = hv;
    }
}

// ---------------- kernel 3: down projection + weight + scatter-add --------------
// grid: (DIM/TN, T_TOK/TM, NEXP), 256 threads
__global__ __launch_bounds__(256)
void down_kernel(const float* __restrict__ W2, const float* __restrict__ b2,
                 float* __restrict__ y) {
    int e = blockIdx.z;
    int cnt = g_cnt[e];
    int m0 = blockIdx.y * TM;
    if (m0 >= cnt) return;
    int n0 = blockIdx.x * TN;

    __shared__ float sA[TKC][TM + 4];
    __shared__ float sB[TKC][TN];
    __shared__ int   sHRow[TM];
    __shared__ int   sTok[TM];
    __shared__ float sW[TM];

    int tid = threadIdx.x;
    if (tid < TM) {
        int m = m0 + tid;
        if (m < cnt) {
            int r = g_rows[e][m];
            sHRow[tid] = r; sTok[tid] = r >> 1; sW[tid] = g_wt[e][m];
        } else { sHRow[tid] = -1; sTok[tid] = -1; sW[tid] = 0.f; }
    }
    __syncthreads();

    const float* W2e = W2 + (size_t)e * INTER * DIM + n0;

    int mb = (tid >> 5) * 8;
    int nb = (tid & 31) * 4;

    int lr = tid >> 2;
    int lq = tid & 3;
    int myH = sHRow[lr];
    const float* aptr = (myH >= 0) ? (g_H + (size_t)myH * INTER + lq * 4) : g_H;

    int kb  = tid >> 5;
    int nbc = (tid & 31) * 4;

    float acc[8][4];
#pragma unroll
    for (int i = 0; i < 8; i++)
#pragma unroll
        for (int j = 0; j < 4; j++) acc[i][j] = 0.f;

    for (int k0 = 0; k0 < INTER; k0 += TKC) {
        float4 av = make_float4(0.f, 0.f, 0.f, 0.f);
        if (myH >= 0) av = *reinterpret_cast<const float4*>(aptr + k0);
        sA[lq * 4 + 0][lr] = av.x;
        sA[lq * 4 + 1][lr] = av.y;
        sA[lq * 4 + 2][lr] = av.z;
        sA[lq * 4 + 3][lr] = av.w;

        *reinterpret_cast<float4*>(&sB[kb][nbc]) =
            *reinterpret_cast<const float4*>(W2e + (size_t)(k0 + kb) * DIM + nbc);
        *reinterpret_cast<float4*>(&sB[kb + 8][nbc]) =
            *reinterpret_cast<const float4*>(W2e + (size_t)(k0 + kb + 8) * DIM + nbc);
        __syncthreads();

#pragma unroll
        for (int kk = 0; kk < TKC; kk++) {
            float a[8], b[4];
#pragma unroll
            for (int i = 0; i < 8; i++) a[i] = sA[kk][mb + i];
#pragma unroll
            for (int j = 0; j < 4; j++) b[j] = sB[kk][nb + j];
#pragma unroll
            for (int i = 0; i < 8; i++)
#pragma unroll
                for (int j = 0; j < 4; j++)
                    acc[i][j] = fmaf(a[i], b[j], acc[i][j]);
        }
        __syncthreads();
    }

    const float4 bv2 = *reinterpret_cast<const float4*>(b2 + (size_t)e * DIM + n0 + nb);
    float b2a[4] = {bv2.x, bv2.y, bv2.z, bv2.w};
#pragma unroll
    for (int i = 0; i < 8; i++) {
        int tok = sTok[mb + i];
        if (tok < 0) continue;
        float w = sW[mb + i];
        float* yr = y + (size_t)tok * DIM + n0 + nb;
#pragma unroll
        for (int j = 0; j < 4; j++)
            atomicAdd(&yr[j], (acc[i][j] + b2a[j]) * w);   // exactly 2 addends/elem -> deterministic
    }
}

// -------------------------------- launcher --------------------------------------
extern "C" void kernel_launch(void* const* d_in, const int* in_sizes, int n_in,
                              void* d_out, int out_size) {
    const float* x  = (const float*)d_in[0];
    const float* Wg = (const float*)d_in[1];
    const float* bg = (const float*)d_in[2];
    const float* W1 = (const float*)d_in[3];
    const float* b1 = (const float*)d_in[4];
    const float* W2 = (const float*)d_in[5];
    const float* b2 = (const float*)d_in[6];
    const float* W3 = (const float*)d_in[7];
    const float* b3 = (const float*)d_in[8];
    float* y = (float*)d_out;

    zero_kernel<<<(T_TOK * DIM / 4 + 255) / 256, 256>>>(y);
    gate_kernel<<<T_TOK, 128>>>(x, Wg, bg);

    dim3 upGrid(INTER / TN, T_TOK / TM, NEXP);
    up_kernel<<<upGrid, 256>>>(x, W1, b1, W3, b3);

    dim3 dnGrid(DIM / TN, T_TOK / TM, NEXP);
    down_kernel<<<dnGrid, 256>>>(W2, b2, y);
}

// round 6
// speedup vs baseline: 1.6802x; 1.6802x over previous
#include <cuda_runtime.h>
#include <cuda_bf16.h>
#include <stdint.h>
#include <math.h>

#define T_TOK 8192
#define DIM 1024
#define NEXP 16
#define INTER 2048
#define NROWS (2*T_TOK)

#define TM 64
#define TN 128
#define TKC 16

// ---------------- device scratch (same footprint as round-1 passing kernel) ----
__device__ int   g_cnt[NEXP];
__device__ int   g_rows[NEXP][T_TOK];   // value = 2*token + slot
__device__ float g_wt[NEXP][T_TOK];
__device__ float g_H[(size_t)NROWS * INTER];   // 134 MB intermediate (fp32)

#define MMA16816(d, a, b0, b1) \
    asm volatile("mma.sync.aligned.m16n8k16.row.col.f32.bf16.bf16.f32 " \
        "{%0,%1,%2,%3}, {%4,%5,%6,%7}, {%8,%9}, {%0,%1,%2,%3};" \
        : "+f"((d)[0]), "+f"((d)[1]), "+f"((d)[2]), "+f"((d)[3]) \
        : "r"((a)[0]), "r"((a)[1]), "r"((a)[2]), "r"((a)[3]), "r"(b0), "r"(b1))

// split one fp32 pair into packed bf16 hi pair + lo (residual) pair
__device__ __forceinline__ void f2bf_pair(float v0, float v1,
                                          uint32_t& hi, uint32_t& lo) {
    __nv_bfloat16 h0 = __float2bfloat16(v0);
    __nv_bfloat16 h1 = __float2bfloat16(v1);
    __nv_bfloat162 hp; hp.x = h0; hp.y = h1;
    __nv_bfloat162 lp;
    lp.x = __float2bfloat16(v0 - __bfloat162float(h0));
    lp.y = __float2bfloat16(v1 - __bfloat162float(h1));
    hi = *reinterpret_cast<uint32_t*>(&hp);
    lo = *reinterpret_cast<uint32_t*>(&lp);
}

// ---------------- kernel 0: reset counters + zero output (R1 verbatim) ---------
__global__ void zero_kernel(float* __restrict__ y) {
    int i = blockIdx.x * blockDim.x + threadIdx.x;
    if (i < NEXP) g_cnt[i] = 0;
    if (i < T_TOK * DIM / 4) {
        float4 z = make_float4(0.f, 0.f, 0.f, 0.f);
        reinterpret_cast<float4*>(y)[i] = z;
    }
}

// ---------------- kernel 1: gate (R1 verbatim) ----------------------------------
__global__ void gate_kernel(const float* __restrict__ x,
                            const float* __restrict__ Wg,
                            const float* __restrict__ bg) {
    int t = blockIdx.x;
    int tid = threadIdx.x;            // 128 threads
    int e = tid & 15;
    int c = tid >> 4;                 // 8 chunks of 128
    __shared__ float part[8][17];
    __shared__ float sc[16];

    const float* xr = x + (size_t)t * DIM;
    const float* wc = Wg + e;
    float s = 0.f;
    int d0 = c * 128;
#pragma unroll 4
    for (int d = 0; d < 128; d++)
        s = fmaf(xr[d0 + d], wc[(size_t)(d0 + d) * NEXP], s);
    part[c][e] = s;
    __syncthreads();

    if (tid < 16) {
        float v = bg[tid];
#pragma unroll
        for (int cc = 0; cc < 8; cc++) v += part[cc][tid];
        sc[tid] = v;
    }
    __syncthreads();

    if (tid == 0) {
        int i1 = 0; float v1 = sc[0];
#pragma unroll
        for (int j = 1; j < 16; j++) if (sc[j] > v1) { v1 = sc[j]; i1 = j; }
        int i2 = -1; float v2 = -3.0e38f;
#pragma unroll
        for (int j = 0; j < 16; j++) if (j != i1 && sc[j] > v2) { v2 = sc[j]; i2 = j; }
        float r  = expf(v2 - v1);     // <= 1, stable
        float w1 = 1.f / (1.f + r);
        float w2 = r   / (1.f + r);
        int p1 = atomicAdd(&g_cnt[i1], 1);
        g_rows[i1][p1] = 2 * t;     g_wt[i1][p1] = w1;
        int p2 = atomicAdd(&g_cnt[i2], 1);
        g_rows[i2][p2] = 2 * t + 1; g_wt[i2][p2] = w2;
    }
}

// ---------------- kernel 2: up projection (R1 loaders + mma compute) ------------
// grid: (INTER/TN, T_TOK/TM, NEXP), 256 threads; 8 warps as 2(m) x 4(n), warp 32x32
__global__ __launch_bounds__(256)
void up_kernel(const float* __restrict__ x,
               const float* __restrict__ W1, const float* __restrict__ b1,
               const float* __restrict__ W3, const float* __restrict__ b3) {
    int e = blockIdx.z;
    int cnt = g_cnt[e];
    int m0 = blockIdx.y * TM;
    if (m0 >= cnt) return;
    int n0 = blockIdx.x * TN;

    __shared__ __align__(16) float sA[TKC][TM + 4];     // [16][68]
    __shared__ __align__(16) float sB1[TKC][TN + 4];    // [16][132]
    __shared__ __align__(16) float sB3[TKC][TN + 4];
    __shared__ int   sTokRow[TM];
    __shared__ int   sOutRow[TM];

    int tid = threadIdx.x;
    int wid = tid >> 5;
    int lane = tid & 31;
    int grp = lane >> 2;           // 0..7
    int tig = lane & 3;            // 0..3
    int wm = (wid >> 2) * 32;      // 0,32
    int wn = (wid & 3) * 32;       // 0,32,64,96

    if (tid < TM) {
        int m = m0 + tid;
        if (m < cnt) { int r = g_rows[e][m]; sTokRow[tid] = r >> 1; sOutRow[tid] = r; }
        else         { sTokRow[tid] = -1;    sOutRow[tid] = -1; }
    }
    __syncthreads();

    const float* W1e = W1 + (size_t)e * DIM * INTER + n0;
    const float* W3e = W3 + (size_t)e * DIM * INTER + n0;

    // R1 loader mappings (verbatim)
    int lr = tid >> 2;             // A row 0..63
    int lq = tid & 3;              // A float4 slot in k
    int myTok = sTokRow[lr];
    const float* aptr = (myTok >= 0) ? (x + (size_t)myTok * DIM + lq * 4) : x;
    int kb  = tid >> 5;            // B k row 0..7
    int nbc = (tid & 31) * 4;      // B col (float4)

    float acc1[2][4][4], acc3[2][4][4];
#pragma unroll
    for (int mt = 0; mt < 2; mt++)
#pragma unroll
        for (int nt = 0; nt < 4; nt++)
#pragma unroll
            for (int j = 0; j < 4; j++) { acc1[mt][nt][j] = 0.f; acc3[mt][nt][j] = 0.f; }

    for (int k0 = 0; k0 < DIM; k0 += TKC) {
        // ---- load (R1 verbatim) ----
        float4 av = make_float4(0.f, 0.f, 0.f, 0.f);
        if (myTok >= 0) av = *reinterpret_cast<const float4*>(aptr + k0);
        sA[lq * 4 + 0][lr] = av.x;
        sA[lq * 4 + 1][lr] = av.y;
        sA[lq * 4 + 2][lr] = av.z;
        sA[lq * 4 + 3][lr] = av.w;

        *reinterpret_cast<float4*>(&sB1[kb][nbc]) =
            *reinterpret_cast<const float4*>(W1e + (size_t)(k0 + kb) * INTER + nbc);
        *reinterpret_cast<float4*>(&sB1[kb + 8][nbc]) =
            *reinterpret_cast<const float4*>(W1e + (size_t)(k0 + kb + 8) * INTER + nbc);
        *reinterpret_cast<float4*>(&sB3[kb][nbc]) =
            *reinterpret_cast<const float4*>(W3e + (size_t)(k0 + kb) * INTER + nbc);
        *reinterpret_cast<float4*>(&sB3[kb + 8][nbc]) =
            *reinterpret_cast<const float4*>(W3e + (size_t)(k0 + kb + 8) * INTER + nbc);
        __syncthreads();

        // ---- fragments: convert fp32 -> split bf16 in registers ----
        uint32_t ah[2][4], al[2][4];
#pragma unroll
        for (int mt = 0; mt < 2; mt++)
#pragma unroll
            for (int r = 0; r < 4; r++) {
                int row = wm + mt * 16 + grp + (r & 1) * 8;
                int kk  = tig * 2 + (r >> 1) * 8;
                f2bf_pair(sA[kk][row], sA[kk + 1][row], ah[mt][r], al[mt][r]);
            }
        uint32_t b1h[4][2], b1l[4][2], b3h[4][2], b3l[4][2];
#pragma unroll
        for (int nt = 0; nt < 4; nt++) {
            int n = wn + nt * 8 + grp;
            f2bf_pair(sB1[tig * 2][n],     sB1[tig * 2 + 1][n], b1h[nt][0], b1l[nt][0]);
            f2bf_pair(sB1[tig * 2 + 8][n], sB1[tig * 2 + 9][n], b1h[nt][1], b1l[nt][1]);
            f2bf_pair(sB3[tig * 2][n],     sB3[tig * 2 + 1][n], b3h[nt][0], b3l[nt][0]);
            f2bf_pair(sB3[tig * 2 + 8][n], sB3[tig * 2 + 9][n], b3h[nt][1], b3l[nt][1]);
        }
#pragma unroll
        for (int mt = 0; mt < 2; mt++)
#pragma unroll
            for (int nt = 0; nt < 4; nt++) {
                MMA16816(acc1[mt][nt], ah[mt], b1h[nt][0], b1h[nt][1]);
                MMA16816(acc1[mt][nt], ah[mt], b1l[nt][0], b1l[nt][1]);
                MMA16816(acc1[mt][nt], al[mt], b1h[nt][0], b1h[nt][1]);
                MMA16816(acc3[mt][nt], ah[mt], b3h[nt][0], b3h[nt][1]);
                MMA16816(acc3[mt][nt], ah[mt], b3l[nt][0], b3l[nt][1]);
                MMA16816(acc3[mt][nt], al[mt], b3h[nt][0], b3h[nt][1]);
            }
        __syncthreads();
    }

    // ---- epilogue: h = silu(z1+b1)*(z3+b3) -> g_H (fp32) ----
#pragma unroll
    for (int mt = 0; mt < 2; mt++) {
#pragma unroll
        for (int half = 0; half < 2; half++) {
            int rloc = wm + mt * 16 + grp + half * 8;
            int hr = sOutRow[rloc];
            if (hr < 0) continue;
            float* pH = g_H + (size_t)hr * INTER + n0;
#pragma unroll
            for (int nt = 0; nt < 4; nt++) {
                int col = wn + nt * 8 + tig * 2;
                float z1a = acc1[mt][nt][half * 2]     + b1[(size_t)e * INTER + n0 + col];
                float z1b = acc1[mt][nt][half * 2 + 1] + b1[(size_t)e * INTER + n0 + col + 1];
                float z3a = acc3[mt][nt][half * 2]     + b3[(size_t)e * INTER + n0 + col];
                float z3b = acc3[mt][nt][half * 2 + 1] + b3[(size_t)e * INTER + n0 + col + 1];
                float2 hv;
                hv.x = (z1a / (1.f + expf(-z1a))) * z3a;
                hv.y = (z1b / (1.f + expf(-z1b))) * z3b;
                *reinterpret_cast<float2*>(pH + col) = hv;
            }
        }
    }
}

// ---------------- kernel 3: down projection (R1 loaders + mma compute) ----------
// grid: (DIM/TN, T_TOK/TM, NEXP), 256 threads; warps 2(m) x 4(n)
__global__ __launch_bounds__(256)
void down_kernel(const float* __restrict__ W2, const float* __restrict__ b2,
                 float* __restrict__ y) {
    int e = blockIdx.z;
    int cnt = g_cnt[e];
    int m0 = blockIdx.y * TM;
    if (m0 >= cnt) return;
    int n0 = blockIdx.x * TN;

    __shared__ __align__(16) float sA[TKC][TM + 4];
    __shared__ __align__(16) float sB[TKC][TN + 4];
    __shared__ int   sHRow[TM];
    __shared__ int   sTok[TM];
    __shared__ float sW[TM];

    int tid = threadIdx.x;
    int wid = tid >> 5;
    int lane = tid & 31;
    int grp = lane >> 2;
    int tig = lane & 3;
    int wm = (wid >> 2) * 32;
    int wn = (wid & 3) * 32;

    if (tid < TM) {
        int m = m0 + tid;
        if (m < cnt) {
            int r = g_rows[e][m];
            sHRow[tid] = r; sTok[tid] = r >> 1; sW[tid] = g_wt[e][m];
        } else { sHRow[tid] = -1; sTok[tid] = -1; sW[tid] = 0.f; }
    }
    __syncthreads();

    const float* W2e = W2 + (size_t)e * INTER * DIM + n0;

    int lr = tid >> 2;
    int lq = tid & 3;
    int myH = sHRow[lr];
    const float* aptr = (myH >= 0) ? (g_H + (size_t)myH * INTER + lq * 4) : g_H;
    int kb  = tid >> 5;
    int nbc = (tid & 31) * 4;

    float acc[2][4][4];
#pragma unroll
    for (int mt = 0; mt < 2; mt++)
#pragma unroll
        for (int nt = 0; nt < 4; nt++)
#pragma unroll
            for (int j = 0; j < 4; j++) acc[mt][nt][j] = 0.f;

    for (int k0 = 0; k0 < INTER; k0 += TKC) {
        float4 av = make_float4(0.f, 0.f, 0.f, 0.f);
        if (myH >= 0) av = *reinterpret_cast<const float4*>(aptr + k0);
        sA[lq * 4 + 0][lr] = av.x;
        sA[lq * 4 + 1][lr] = av.y;
        sA[lq * 4 + 2][lr] = av.z;
        sA[lq * 4 + 3][lr] = av.w;

        *reinterpret_cast<float4*>(&sB[kb][nbc]) =
            *reinterpret_cast<const float4*>(W2e + (size_t)(k0 + kb) * DIM + nbc);
        *reinterpret_cast<float4*>(&sB[kb + 8][nbc]) =
            *reinterpret_cast<const float4*>(W2e + (size_t)(k0 + kb + 8) * DIM + nbc);
        __syncthreads();

        uint32_t ah[2][4], al[2][4];
#pragma unroll
        for (int mt = 0; mt < 2; mt++)
#pragma unroll
            for (int r = 0; r < 4; r++) {
                int row = wm + mt * 16 + grp + (r & 1) * 8;
                int kk  = tig * 2 + (r >> 1) * 8;
                f2bf_pair(sA[kk][row], sA[kk + 1][row], ah[mt][r], al[mt][r]);
            }
        uint32_t bh[4][2], bl[4][2];
#pragma unroll
        for (int nt = 0; nt < 4; nt++) {
            int n = wn + nt * 8 + grp;
            f2bf_pair(sB[tig * 2][n],     sB[tig * 2 + 1][n], bh[nt][0], bl[nt][0]);
            f2bf_pair(sB[tig * 2 + 8][n], sB[tig * 2 + 9][n], bh[nt][1], bl[nt][1]);
        }
#pragma unroll
        for (int mt = 0; mt < 2; mt++)
#pragma unroll
            for (int nt = 0; nt < 4; nt++) {
                MMA16816(acc[mt][nt], ah[mt], bh[nt][0], bh[nt][1]);
                MMA16816(acc[mt][nt], ah[mt], bl[nt][0], bl[nt][1]);
                MMA16816(acc[mt][nt], al[mt], bh[nt][0], bh[nt][1]);
            }
        __syncthreads();
    }

    // epilogue: weight + scatter-add (exactly 2 addends/element -> deterministic)
#pragma unroll
    for (int mt = 0; mt < 2; mt++) {
#pragma unroll
        for (int half = 0; half < 2; half++) {
            int rloc = wm + mt * 16 + grp + half * 8;
            int tok = sTok[rloc];
            if (tok < 0) continue;
            float w = sW[rloc];
            float* yr = y + (size_t)tok * DIM + n0;
#pragma unroll
            for (int nt = 0; nt < 4; nt++) {
                int col = wn + nt * 8 + tig * 2;
                float vb0 = b2[(size_t)e * DIM + n0 + col];
                float vb1 = b2[(size_t)e * DIM + n0 + col + 1];
                atomicAdd(yr + col,     (acc[mt][nt][half * 2]     + vb0) * w);
                atomicAdd(yr + col + 1, (acc[mt][nt][half * 2 + 1] + vb1) * w);
            }
        }
    }
}

// -------------------------------- launcher --------------------------------------
extern "C" void kernel_launch(void* const* d_in, const int* in_sizes, int n_in,
                              void* d_out, int out_size) {
    const float* x  = (const float*)d_in[0];
    const float* Wg = (const float*)d_in[1];
    const float* bg = (const float*)d_in[2];
    const float* W1 = (const float*)d_in[3];
    const float* b1 = (const float*)d_in[4];
    const float* W2 = (const float*)d_in[5];
    const float* b2 = (const float*)d_in[6];
    const float* W3 = (const float*)d_in[7];
    const float* b3 = (const float*)d_in[8];
    float* y = (float*)d_out;

    zero_kernel<<<(T_TOK * DIM / 4 + 255) / 256, 256>>>(y);
    gate_kernel<<<T_TOK, 128>>>(x, Wg, bg);

    dim3 upGrid(INTER / TN, T_TOK / TM, NEXP);
    up_kernel<<<upGrid, 256>>>(x, W1, b1, W3, b3);

    dim3 dnGrid(DIM / TN, T_TOK / TM, NEXP);
    down_kernel<<<dnGrid, 256>>>(W2, b2, y);
}

// round 7
// speedup vs baseline: 2.0323x; 1.2095x over previous
#include <cuda_runtime.h>
#include <cuda_bf16.h>
#include <stdint.h>
#include <math.h>

#define T_TOK 8192
#define DIM 1024
#define NEXP 16
#define INTER 2048
#define NROWS (2*T_TOK)

#define TM 64
#define TN 128
#define TKC 16
#define KW 12          // words per smem row (8 data words = 16 bf16, +4 pad)

// ---------------- device scratch ----------------
__device__ int   g_cnt[NEXP];
__device__ int   g_rows[NEXP][T_TOK];   // value = 2*token + slot
__device__ float g_wt[NEXP][T_TOK];
__device__ float g_H[(size_t)NROWS * INTER];   // fp32 intermediate

#define MMA16816(d, a, b0, b1) \
    asm volatile("mma.sync.aligned.m16n8k16.row.col.f32.bf16.bf16.f32 " \
        "{%0,%1,%2,%3}, {%4,%5,%6,%7}, {%8,%9}, {%0,%1,%2,%3};" \
        : "+f"((d)[0]), "+f"((d)[1]), "+f"((d)[2]), "+f"((d)[3]) \
        : "r"((a)[0]), "r"((a)[1]), "r"((a)[2]), "r"((a)[3]), "r"(b0), "r"(b1))

// split fp32 pair -> packed bf16 hi pair + residual lo pair (lo16 = v0)
__device__ __forceinline__ void f2bf_pair(float v0, float v1,
                                          uint32_t& hi, uint32_t& lo) {
    uint32_t h;
    asm("cvt.rn.bf16x2.f32 %0, %1, %2;" : "=r"(h) : "f"(v1), "f"(v0));
    float h0 = __uint_as_float(h << 16);
    float h1 = __uint_as_float(h & 0xffff0000u);
    uint32_t l;
    asm("cvt.rn.bf16x2.f32 %0, %1, %2;" : "=r"(l) : "f"(v1 - h1), "f"(v0 - h0));
    hi = h; lo = l;
}

// ---------------- kernel 0: reset counters + zero output ----------------
__global__ void zero_kernel(float* __restrict__ y) {
    int i = blockIdx.x * blockDim.x + threadIdx.x;
    if (i < NEXP) g_cnt[i] = 0;
    if (i < T_TOK * DIM / 4) {
        float4 z = make_float4(0.f, 0.f, 0.f, 0.f);
        reinterpret_cast<float4*>(y)[i] = z;
    }
}

// ---------------- kernel 1: gate (unchanged, passing) ----------------
__global__ void gate_kernel(const float* __restrict__ x,
                            const float* __restrict__ Wg,
                            const float* __restrict__ bg) {
    int t = blockIdx.x;
    int tid = threadIdx.x;
    int e = tid & 15;
    int c = tid >> 4;
    __shared__ float part[8][17];
    __shared__ float sc[16];

    const float* xr = x + (size_t)t * DIM;
    const float* wc = Wg + e;
    float s = 0.f;
    int d0 = c * 128;
#pragma unroll 4
    for (int d = 0; d < 128; d++)
        s = fmaf(xr[d0 + d], wc[(size_t)(d0 + d) * NEXP], s);
    part[c][e] = s;
    __syncthreads();

    if (tid < 16) {
        float v = bg[tid];
#pragma unroll
        for (int cc = 0; cc < 8; cc++) v += part[cc][tid];
        sc[tid] = v;
    }
    __syncthreads();

    if (tid == 0) {
        int i1 = 0; float v1 = sc[0];
#pragma unroll
        for (int j = 1; j < 16; j++) if (sc[j] > v1) { v1 = sc[j]; i1 = j; }
        int i2 = -1; float v2 = -3.0e38f;
#pragma unroll
        for (int j = 0; j < 16; j++) if (j != i1 && sc[j] > v2) { v2 = sc[j]; i2 = j; }
        float r  = expf(v2 - v1);
        float w1 = 1.f / (1.f + r);
        float w2 = r   / (1.f + r);
        int p1 = atomicAdd(&g_cnt[i1], 1);
        g_rows[i1][p1] = 2 * t;     g_wt[i1][p1] = w1;
        int p2 = atomicAdd(&g_cnt[i2], 1);
        g_rows[i2][p2] = 2 * t + 1; g_wt[i2][p2] = w2;
    }
}

// ---------------- kernel 2: up projection ----------------
// grid: (INTER/TN, T_TOK/TM, NEXP), 256 threads; warps 2(m) x 4(n), warp 32x32
__global__ __launch_bounds__(256, 2)
void up_kernel(const float* __restrict__ x,
               const float* __restrict__ W1, const float* __restrict__ b1,
               const float* __restrict__ W3, const float* __restrict__ b3) {
    int e = blockIdx.z;
    int cnt = g_cnt[e];
    int m0 = blockIdx.y * TM;
    if (m0 >= cnt) return;
    int n0 = blockIdx.x * TN;

    __shared__ __align__(16) uint32_t sAh[TM*KW],  sAl[TM*KW];     // [row][k] bf16 pairs
    __shared__ __align__(16) uint32_t sB1h[TN*KW], sB1l[TN*KW];    // [n][k]
    __shared__ __align__(16) uint32_t sB3h[TN*KW], sB3l[TN*KW];
    __shared__ int sTokRow[TM];
    __shared__ int sOutRow[TM];

    int tid = threadIdx.x;
    int wid = tid >> 5;
    int lane = tid & 31;
    int grp = lane >> 2;           // 0..7
    int tig = lane & 3;            // 0..3
    int wm = (wid >> 2) * 32;      // 0,32
    int wn = (wid & 3) * 32;       // 0,32,64,96

    if (tid < TM) {
        int m = m0 + tid;
        if (m < cnt) { int r = g_rows[e][m]; sTokRow[tid] = r >> 1; sOutRow[tid] = r; }
        else         { sTokRow[tid] = -1;    sOutRow[tid] = -1; }
    }
    __syncthreads();

    const float* W1e = W1 + (size_t)e * DIM * INTER + n0;   // [k][n]
    const float* W3e = W3 + (size_t)e * DIM * INTER + n0;

    // A loader: row = tid>>2 (0..63), q = tid&3 -> 4 k-elems
    int arow = tid >> 2, aq = tid & 3;
    int myTok = sTokRow[arow];
    const float* aptr = (myTok >= 0) ? (x + (size_t)myTok * DIM + aq * 4) : x;
    // B loader: n = tid&127, kg = (tid>>7)*8 -> 8 k-elems (transpose in regs)
    int bn = tid & 127;
    int bkg = (tid >> 7) * 8;

    float4 rA;
    float rB1[8], rB3[8];
    const float4 zf4 = make_float4(0.f, 0.f, 0.f, 0.f);

    auto fetch = [&](int k0) {
        rA = (myTok >= 0) ? *reinterpret_cast<const float4*>(aptr + k0) : zf4;
#pragma unroll
        for (int j = 0; j < 8; j++) {
            rB1[j] = W1e[(size_t)(k0 + bkg + j) * INTER + bn];
            rB3[j] = W3e[(size_t)(k0 + bkg + j) * INTER + bn];
        }
    };
    auto stage = [&]() {
        uint32_t h0, l0, h1, l1;
        f2bf_pair(rA.x, rA.y, h0, l0);
        f2bf_pair(rA.z, rA.w, h1, l1);
        int ab = arow * KW + aq * 2;
        *reinterpret_cast<uint2*>(&sAh[ab]) = make_uint2(h0, h1);
        *reinterpret_cast<uint2*>(&sAl[ab]) = make_uint2(l0, l1);
        int bb = bn * KW + (bkg >> 1);
        uint32_t bh[4], bl[4];
#pragma unroll
        for (int j = 0; j < 4; j++) f2bf_pair(rB1[2*j], rB1[2*j+1], bh[j], bl[j]);
        *reinterpret_cast<uint4*>(&sB1h[bb]) = make_uint4(bh[0], bh[1], bh[2], bh[3]);
        *reinterpret_cast<uint4*>(&sB1l[bb]) = make_uint4(bl[0], bl[1], bl[2], bl[3]);
#pragma unroll
        for (int j = 0; j < 4; j++) f2bf_pair(rB3[2*j], rB3[2*j+1], bh[j], bl[j]);
        *reinterpret_cast<uint4*>(&sB3h[bb]) = make_uint4(bh[0], bh[1], bh[2], bh[3]);
        *reinterpret_cast<uint4*>(&sB3l[bb]) = make_uint4(bl[0], bl[1], bl[2], bl[3]);
    };

    float acc1[2][4][4], acc3[2][4][4];
#pragma unroll
    for (int mt = 0; mt < 2; mt++)
#pragma unroll
        for (int nt = 0; nt < 4; nt++)
#pragma unroll
            for (int j = 0; j < 4; j++) { acc1[mt][nt][j] = 0.f; acc3[mt][nt][j] = 0.f; }

    const int NC = DIM / TKC;   // 64
    fetch(0);
    for (int c = 0; c < NC; c++) {
        stage();
        __syncthreads();
        if (c + 1 < NC) fetch((c + 1) * TKC);   // overlap LDG with MMA

        uint32_t ah[2][4], al[2][4];
#pragma unroll
        for (int mt = 0; mt < 2; mt++) {
            int r0 = (wm + mt * 16 + grp) * KW;
            int r1 = r0 + 8 * KW;
            ah[mt][0] = sAh[r0 + tig];     ah[mt][1] = sAh[r1 + tig];
            ah[mt][2] = sAh[r0 + tig + 4]; ah[mt][3] = sAh[r1 + tig + 4];
            al[mt][0] = sAl[r0 + tig];     al[mt][1] = sAl[r1 + tig];
            al[mt][2] = sAl[r0 + tig + 4]; al[mt][3] = sAl[r1 + tig + 4];
        }
#pragma unroll
        for (int nt = 0; nt < 4; nt++) {
            int nb = (wn + nt * 8 + grp) * KW;
            uint32_t b1h0 = sB1h[nb + tig], b1h1 = sB1h[nb + tig + 4];
            uint32_t b1l0 = sB1l[nb + tig], b1l1 = sB1l[nb + tig + 4];
            uint32_t b3h0 = sB3h[nb + tig], b3h1 = sB3h[nb + tig + 4];
            uint32_t b3l0 = sB3l[nb + tig], b3l1 = sB3l[nb + tig + 4];
#pragma unroll
            for (int mt = 0; mt < 2; mt++) {
                MMA16816(acc1[mt][nt], ah[mt], b1h0, b1h1);
                MMA16816(acc1[mt][nt], ah[mt], b1l0, b1l1);
                MMA16816(acc1[mt][nt], al[mt], b1h0, b1h1);
                MMA16816(acc3[mt][nt], ah[mt], b3h0, b3h1);
                MMA16816(acc3[mt][nt], ah[mt], b3l0, b3l1);
                MMA16816(acc3[mt][nt], al[mt], b3h0, b3h1);
            }
        }
        __syncthreads();
    }

    // epilogue: h = silu(z1+b1)*(z3+b3) -> g_H (unchanged from passing R6)
    const float* pb1 = b1 + (size_t)e * INTER + n0;
    const float* pb3 = b3 + (size_t)e * INTER + n0;
#pragma unroll
    for (int mt = 0; mt < 2; mt++) {
#pragma unroll
        for (int half = 0; half < 2; half++) {
            int rloc = wm + mt * 16 + grp + half * 8;
            int hr = sOutRow[rloc];
            if (hr < 0) continue;
            float* pH = g_H + (size_t)hr * INTER + n0;
#pragma unroll
            for (int nt = 0; nt < 4; nt++) {
                int col = wn + nt * 8 + tig * 2;
                float z1a = acc1[mt][nt][half * 2]     + pb1[col];
                float z1b = acc1[mt][nt][half * 2 + 1] + pb1[col + 1];
                float z3a = acc3[mt][nt][half * 2]     + pb3[col];
                float z3b = acc3[mt][nt][half * 2 + 1] + pb3[col + 1];
                float2 hv;
                hv.x = (z1a / (1.f + expf(-z1a))) * z3a;
                hv.y = (z1b / (1.f + expf(-z1b))) * z3b;
                *reinterpret_cast<float2*>(pH + col) = hv;
            }
        }
    }
}

// ---------------- kernel 3: down projection ----------------
// grid: (DIM/TN, T_TOK/TM, NEXP), 256 threads; warps 2(m) x 4(n)
__global__ __launch_bounds__(256, 2)
void down_kernel(const float* __restrict__ W2, const float* __restrict__ b2,
                 float* __restrict__ y) {
    int e = blockIdx.z;
    int cnt = g_cnt[e];
    int m0 = blockIdx.y * TM;
    if (m0 >= cnt) return;
    int n0 = blockIdx.x * TN;

    __shared__ __align__(16) uint32_t sAh[TM*KW], sAl[TM*KW];
    __shared__ __align__(16) uint32_t sBh[TN*KW], sBl[TN*KW];
    __shared__ int   sHRow[TM];
    __shared__ int   sTok[TM];
    __shared__ float sW[TM];

    int tid = threadIdx.x;
    int wid = tid >> 5;
    int lane = tid & 31;
    int grp = lane >> 2;
    int tig = lane & 3;
    int wm = (wid >> 2) * 32;
    int wn = (wid & 3) * 32;

    if (tid < TM) {
        int m = m0 + tid;
        if (m < cnt) {
            int r = g_rows[e][m];
            sHRow[tid] = r; sTok[tid] = r >> 1; sW[tid] = g_wt[e][m];
        } else { sHRow[tid] = -1; sTok[tid] = -1; sW[tid] = 0.f; }
    }
    __syncthreads();

    const float* W2e = W2 + (size_t)e * INTER * DIM + n0;   // [k][n]

    int arow = tid >> 2, aq = tid & 3;
    int myH = sHRow[arow];
    const float* aptr = (myH >= 0) ? (g_H + (size_t)myH * INTER + aq * 4) : g_H;
    int bn = tid & 127;
    int bkg = (tid >> 7) * 8;

    float4 rA;
    float rB[8];
    const float4 zf4 = make_float4(0.f, 0.f, 0.f, 0.f);

    auto fetch = [&](int k0) {
        rA = (myH >= 0) ? *reinterpret_cast<const float4*>(aptr + k0) : zf4;
#pragma unroll
        for (int j = 0; j < 8; j++)
            rB[j] = W2e[(size_t)(k0 + bkg + j) * DIM + bn];
    };
    auto stage = [&]() {
        uint32_t h0, l0, h1, l1;
        f2bf_pair(rA.x, rA.y, h0, l0);
        f2bf_pair(rA.z, rA.w, h1, l1);
        int ab = arow * KW + aq * 2;
        *reinterpret_cast<uint2*>(&sAh[ab]) = make_uint2(h0, h1);
        *reinterpret_cast<uint2*>(&sAl[ab]) = make_uint2(l0, l1);
        int bb = bn * KW + (bkg >> 1);
        uint32_t bh[4], bl[4];
#pragma unroll
        for (int j = 0; j < 4; j++) f2bf_pair(rB[2*j], rB[2*j+1], bh[j], bl[j]);
        *reinterpret_cast<uint4*>(&sBh[bb]) = make_uint4(bh[0], bh[1], bh[2], bh[3]);
        *reinterpret_cast<uint4*>(&sBl[bb]) = make_uint4(bl[0], bl[1], bl[2], bl[3]);
    };

    float acc[2][4][4];
#pragma unroll
    for (int mt = 0; mt < 2; mt++)
#pragma unroll
        for (int nt = 0; nt < 4; nt++)
#pragma unroll
            for (int j = 0; j < 4; j++) acc[mt][nt][j] = 0.f;

    const int NC = INTER / TKC;   // 128
    fetch(0);
    for (int c = 0; c < NC; c++) {
        stage();
        __syncthreads();
        if (c + 1 < NC) fetch((c + 1) * TKC);

        uint32_t ah[2][4], al[2][4];
#pragma unroll
        for (int mt = 0; mt < 2; mt++) {
            int r0 = (wm + mt * 16 + grp) * KW;
            int r1 = r0 + 8 * KW;
            ah[mt][0] = sAh[r0 + tig];     ah[mt][1] = sAh[r1 + tig];
            ah[mt][2] = sAh[r0 + tig + 4]; ah[mt][3] = sAh[r1 + tig + 4];
            al[mt][0] = sAl[r0 + tig];     al[mt][1] = sAl[r1 + tig];
            al[mt][2] = sAl[r0 + tig + 4]; al[mt][3] = sAl[r1 + tig + 4];
        }
#pragma unroll
        for (int nt = 0; nt < 4; nt++) {
            int nb = (wn + nt * 8 + grp) * KW;
            uint32_t bh0 = sBh[nb + tig], bh1 = sBh[nb + tig + 4];
            uint32_t bl0 = sBl[nb + tig], bl1 = sBl[nb + tig + 4];
#pragma unroll
            for (int mt = 0; mt < 2; mt++) {
                MMA16816(acc[mt][nt], ah[mt], bh0, bh1);
                MMA16816(acc[mt][nt], ah[mt], bl0, bl1);
                MMA16816(acc[mt][nt], al[mt], bh0, bh1);
            }
        }
        __syncthreads();
    }

    // epilogue: weight + deterministic 2-addend scatter-add (unchanged)
    const float* pb2 = b2 + (size_t)e * DIM + n0;
#pragma unroll
    for (int mt = 0; mt < 2; mt++) {
#pragma unroll
        for (int half = 0; half < 2; half++) {
            int rloc = wm + mt * 16 + grp + half * 8;
            int tok = sTok[rloc];
            if (tok < 0) continue;
            float w = sW[rloc];
            float* yr = y + (size_t)tok * DIM + n0;
#pragma unroll
            for (int nt = 0; nt < 4; nt++) {
                int col = wn + nt * 8 + tig * 2;
                atomicAdd(yr + col,     (acc[mt][nt][half * 2]     + pb2[col])     * w);
                atomicAdd(yr + col + 1, (acc[mt][nt][half * 2 + 1] + pb2[col + 1]) * w);
            }
        }
    }
}

// -------------------------------- launcher --------------------------------------
extern "C" void kernel_launch(void* const* d_in, const int* in_sizes, int n_in,
                              void* d_out, int out_size) {
    const float* x  = (const float*)d_in[0];
    const float* Wg = (const float*)d_in[1];
    const float* bg = (const float*)d_in[2];
    const float* W1 = (const float*)d_in[3];
    const float* b1 = (const float*)d_in[4];
    const float* W2 = (const float*)d_in[5];
    const float* b2 = (const float*)d_in[6];
    const float* W3 = (const float*)d_in[7];
    const float* b3 = (const float*)d_in[8];
    float* y = (float*)d_out;

    zero_kernel<<<(T_TOK * DIM / 4 + 255) / 256, 256>>>(y);
    gate_kernel<<<T_TOK, 128>>>(x, Wg, bg);

    dim3 upGrid(INTER / TN, T_TOK / TM, NEXP);
    up_kernel<<<upGrid, 256>>>(x, W1, b1, W3, b3);

    dim3 dnGrid(DIM / TN, T_TOK / TM, NEXP);
    down_kernel<<<dnGrid, 256>>>(W2, b2, y);
}